// round 8
// baseline (speedup 1.0000x reference)
#include <cuda_runtime.h>
#include <math.h>

#define T_   1024
#define B_   8
#define E_   1024
#define H_   16
#define HD   64
#define NB   4
#define DIN  256
#define TOPK 16
#define ROWS (T_*B_)          // 8192
#define BE   (B_*E_)          // 8192
#define SCALING 0.125f        // 64^-0.5

// ---------- scratch (device globals; no runtime allocation) ----------
__device__ float g_q[ROWS * E_];
__device__ float g_k[ROWS * E_];
__device__ float g_v[ROWS * E_];
__device__ float g_ctx[ROWS * E_];

// ---------- packed f32x2 helpers (exact lane-wise IEEE rn) ----------
__device__ __forceinline__ void dup2(unsigned long long& d, float f) {
    asm("mov.b64 %0, {%1, %1};" : "=l"(d) : "r"(__float_as_uint(f)));
}
__device__ __forceinline__ void fma2(unsigned long long& d,
                                     unsigned long long a,
                                     unsigned long long b,
                                     unsigned long long c) {
    asm("fma.rn.f32x2 %0, %1, %2, %3;" : "=l"(d) : "l"(a), "l"(b), "l"(c));
}
__device__ __forceinline__ void unpack2(float& lo, float& hi, unsigned long long p) {
    unsigned l, h;
    asm("mov.b64 {%0, %1}, %2;" : "=r"(l), "=r"(h) : "l"(p));
    lo = __uint_as_float(l); hi = __uint_as_float(h);
}

// =====================================================================
// Double-buffered block-diagonal GEMM core (BK=16, FFMA2).
// B read as 4x LDS.64 at columns {2tx+32j, 2tx+1+32j} -> conflict-free
// (lanes 0-15 hit banks 0,2,...,30). Per-element accumulation order
// unchanged (k ascending) -> bitwise-identical outputs.
// =====================================================================
__device__ __forceinline__ void gemm_core(
    const float* __restrict__ X, const float* __restrict__ W,
    const float* __restrict__ bias, float* __restrict__ Y,
    float scale, int nb)
{
    const int m0 = blockIdx.x * 128;
    const int n0 = blockIdx.y * 128;
    const float* Wn = W + nb * DIN * DIN;

    __shared__ __align__(16) float As[2][16][128];
    __shared__ __align__(16) float Bs[2][16][128];

    const int tid = threadIdx.x;
    const int ty  = tid >> 4;
    const int tx2 = (tid & 15) * 2;       // column pair base
    const int arow = tid >> 1;
    const int akc  = (tid & 1) * 8;
    const int bkr  = tid >> 4;
    const int bcol = (tid & 15) * 8;

    const float* Xb = X + (long)m0 * E_ + nb * DIN;
    const float* Ap = Xb + (long)arow * E_;

    // prologue: stage 0
    {
        float4 a0 = *(const float4*)(Ap + akc);
        float4 a1 = *(const float4*)(Ap + akc + 4);
        float4 b0 = *(const float4*)(Wn + bkr * DIN + n0 + bcol);
        float4 b1 = *(const float4*)(Wn + bkr * DIN + n0 + bcol + 4);
        As[0][akc+0][arow] = a0.x; As[0][akc+1][arow] = a0.y;
        As[0][akc+2][arow] = a0.z; As[0][akc+3][arow] = a0.w;
        As[0][akc+4][arow] = a1.x; As[0][akc+5][arow] = a1.y;
        As[0][akc+6][arow] = a1.z; As[0][akc+7][arow] = a1.w;
        *(float4*)&Bs[0][bkr][bcol]     = b0;
        *(float4*)&Bs[0][bkr][bcol + 4] = b1;
    }
    __syncthreads();

    unsigned long long accp[8][4];
#pragma unroll
    for (int i = 0; i < 8; i++)
#pragma unroll
        for (int j = 0; j < 4; j++) accp[i][j] = 0ull;

    for (int k0 = 0; k0 < 16; k0++) {
        const int cur = k0 & 1;
        float4 a0, a1, b0, b1;
        if (k0 < 15) {
            const int kn = (k0 + 1) * 16;
            a0 = *(const float4*)(Ap + kn + akc);
            a1 = *(const float4*)(Ap + kn + akc + 4);
            b0 = *(const float4*)(Wn + (kn + bkr) * DIN + n0 + bcol);
            b1 = *(const float4*)(Wn + (kn + bkr) * DIN + n0 + bcol + 4);
        }
#pragma unroll
        for (int kk = 0; kk < 16; kk++) {
            float af[8];
            *(float4*)(af)     = *(const float4*)&As[cur][kk][ty * 8];
            *(float4*)(af + 4) = *(const float4*)&As[cur][kk][ty * 8 + 4];
            unsigned long long bp[4];
#pragma unroll
            for (int j = 0; j < 4; j++)
                bp[j] = *(const unsigned long long*)&Bs[cur][kk][tx2 + 32 * j];
#pragma unroll
            for (int i = 0; i < 8; i++) {
                unsigned long long aa;
                dup2(aa, af[i]);
                fma2(accp[i][0], aa, bp[0], accp[i][0]);
                fma2(accp[i][1], aa, bp[1], accp[i][1]);
                fma2(accp[i][2], aa, bp[2], accp[i][2]);
                fma2(accp[i][3], aa, bp[3], accp[i][3]);
            }
        }
        if (k0 < 15) {
            const int nxt = cur ^ 1;
            As[nxt][akc+0][arow] = a0.x; As[nxt][akc+1][arow] = a0.y;
            As[nxt][akc+2][arow] = a0.z; As[nxt][akc+3][arow] = a0.w;
            As[nxt][akc+4][arow] = a1.x; As[nxt][akc+5][arow] = a1.y;
            As[nxt][akc+6][arow] = a1.z; As[nxt][akc+7][arow] = a1.w;
            *(float4*)&Bs[nxt][bkr][bcol]     = b0;
            *(float4*)&Bs[nxt][bkr][bcol + 4] = b1;
        }
        __syncthreads();
    }

    float2 bj[4];
#pragma unroll
    for (int j = 0; j < 4; j++) {
        bj[j].x = bias[nb * DIN + n0 + tx2 + 32 * j];
        bj[j].y = bias[nb * DIN + n0 + tx2 + 32 * j + 1];
    }

#pragma unroll
    for (int i = 0; i < 8; i++) {
        const long row = m0 + ty * 8 + i;
        float* yp = Y + row * E_ + nb * DIN + n0;
#pragma unroll
        for (int j = 0; j < 4; j++) {
            float lo, hi;
            unpack2(lo, hi, accp[i][j]);
            *(float2*)(yp + tx2 + 32 * j) =
                make_float2((lo + bj[j].x) * scale, (hi + bj[j].y) * scale);
        }
    }
}

// fused QKV: grid.z = 12 (op = z>>2, nb = z&3)
__global__ void __launch_bounds__(256) qkv_gemm(
    const float* __restrict__ Q, const float* __restrict__ Kin,
    const float* __restrict__ V,
    const float* __restrict__ Wq, const float* __restrict__ bq,
    const float* __restrict__ Wk, const float* __restrict__ bk,
    const float* __restrict__ Wv, const float* __restrict__ bv,
    float* __restrict__ Yq, float* __restrict__ Yk, float* __restrict__ Yv)
{
    const int op = blockIdx.z >> 2;
    const int nb = blockIdx.z & 3;
    if (op == 0)      gemm_core(Q,   Wq, bq, Yq, SCALING, nb);
    else if (op == 1) gemm_core(Kin, Wk, bk, Yk, 1.0f,    nb);
    else              gemm_core(V,   Wv, bv, Yv, 1.0f,    nb);
}

__global__ void __launch_bounds__(256) o_gemm(
    const float* __restrict__ X, const float* __restrict__ W,
    const float* __restrict__ bias, float* __restrict__ Y)
{
    gemm_core(X, W, bias, Y, 1.0f, blockIdx.z);
}

// =====================================================================
// Fused attention. QT=16, 512 threads, 2 blocks/SM.
// Warps 0-7: scores (2 q-pairs x 32 keys each) on current K buffer.
// Warps 8-15: producers, prefetch next 64-key tile (double buffer).
// Each f32x2 lane = independent exact d-ascending fmaf chain ->
// bitwise-identical scores -> identical top-k selection.
// =====================================================================
#define QT  16
#define KT  64
#define SP  1032
#define NTH 512

__device__ __forceinline__ unsigned fmono(float f) {
    unsigned b = __float_as_uint(f);
    return (b & 0x80000000u) ? ~b : (b | 0x80000000u);
}
__device__ __forceinline__ float fdemono(unsigned m) {
    unsigned b = (m & 0x80000000u) ? (m & 0x7fffffffu) : ~m;
    return __uint_as_float(b);
}

__global__ void __launch_bounds__(NTH, 2) attn_kernel(
    const float* __restrict__ qg, const float* __restrict__ kg,
    const float* __restrict__ vg, float* __restrict__ ctxg)
{
    extern __shared__ float sm[];
    float* S    = sm;                      // QT*SP              (66048 B)
    float* ks   = S + QT * SP;             // 2 x 64 x 64 swizzled (32768 B)
    float* qp   = ks + 2 * KT * 64;        // 8 pairs x 64 d x float2 (4096 B)
    float* tpp  = qp + 8 * 64 * 2;         // QT*16
    int*   tpi  = (int*)(tpp + QT * TOPK); // QT*16

    const int tid = threadIdx.x;
    const int qt  = blockIdx.x;            // 0..63
    const int bh  = blockIdx.y;            // 0..127
    const int bb  = bh >> 4;
    const int hh  = bh & 15;
    const long base = (long)bb * E_ + hh * HD;

    const int lane = tid & 31;
    const int w    = tid >> 5;             // warp 0..15

    // ---- build q pairs: qp[pair][d] = {q[2p][d], q[2p+1][d]} ----
    {
        const int p = tid >> 6;            // 0..7
        const int d = tid & 63;
        const float* q0 = qg + (long)(qt * QT + 2 * p) * BE + base + d;
        *(float2*)&qp[(p * 64 + d) * 2] = make_float2(q0[0], q0[BE]);
    }

    // ---- initial K tile (kt=0) into buffer 0, all threads ----
#pragma unroll
    for (int f = tid; f < KT * 16; f += NTH) {
        int key = f >> 4, d4x = f & 15;
        float4 v4 = *(const float4*)(kg + (long)key * BE + base + d4x * 4);
        *(float4*)&ks[key * 64 + ((d4x ^ (key & 7)) << 2)] = v4;
    }
    __syncthreads();

    // score warp roles (w<8): pg = pair group (2 pairs), s = key half
    const int pg = w >> 1;                 // 0..3 -> pairs pg*2, pg*2+1
    const int s  = w & 1;                  // keys s*32 + lane
    const int lane7 = lane & 7;

    for (int kt = 0; kt < T_ / KT; kt++) {
        const int cur = kt & 1;
        if (w >= 8) {
            if (kt < T_ / KT - 1) {        // prefetch next tile
                float* kd = ks + (cur ^ 1) * KT * 64;
                const float* kgn = kg + (long)(kt + 1) * KT * BE + base;
                for (int f = tid - 256; f < KT * 16; f += 256) {
                    int key = f >> 4, d4x = f & 15;
                    float4 v4 = *(const float4*)(kgn + (long)key * BE + d4x * 4);
                    *(float4*)&kd[key * 64 + ((d4x ^ (key & 7)) << 2)] = v4;
                }
            }
        } else {
            const float* ka = ks + cur * KT * 64 + (s * 32 + lane) * 64;
            const float* qb = qp + (pg * 2) * 64 * 2;

            unsigned long long acc0 = 0ull, acc1 = 0ull;
#pragma unroll
            for (int d4 = 0; d4 < 16; d4++) {
                float4 Kv = *(const float4*)(ka + ((d4 ^ lane7) << 2));
                unsigned long long kd0, kd1, kd2, kd3;
                dup2(kd0, Kv.x); dup2(kd1, Kv.y);
                dup2(kd2, Kv.z); dup2(kd3, Kv.w);

                ulonglong2 qa01 = *(const ulonglong2*)(qb + d4 * 8);
                ulonglong2 qa23 = *(const ulonglong2*)(qb + d4 * 8 + 4);
                fma2(acc0, qa01.x, kd0, acc0);
                fma2(acc0, qa01.y, kd1, acc0);
                fma2(acc0, qa23.x, kd2, acc0);
                fma2(acc0, qa23.y, kd3, acc0);

                ulonglong2 qb01 = *(const ulonglong2*)(qb + 128 + d4 * 8);
                ulonglong2 qb23 = *(const ulonglong2*)(qb + 128 + d4 * 8 + 4);
                fma2(acc1, qb01.x, kd0, acc1);
                fma2(acc1, qb01.y, kd1, acc1);
                fma2(acc1, qb23.x, kd2, acc1);
                fma2(acc1, qb23.y, kd3, acc1);
            }

            const int col = kt * KT + s * 32 + lane;
            float lo, hi;
            unpack2(lo, hi, acc0);
            S[(pg * 4 + 0) * SP + col] = lo;
            S[(pg * 4 + 1) * SP + col] = hi;
            unpack2(lo, hi, acc1);
            S[(pg * 4 + 2) * SP + col] = lo;
            S[(pg * 4 + 3) * SP + col] = hi;
        }
        __syncthreads();
    }

    // ---- per-row top-16 + softmax: warp w owns row w ----
    {
        float* Sr = S + w * SP;

        float v0 = -INFINITY, v1 = -INFINITY, v2 = -INFINITY, v3 = -INFINITY;
        int   p0 = 0, p1 = 0, p2 = 0, p3 = 0;
#pragma unroll 8
        for (int t = 0; t < 32; t++) {
            float nv = Sr[lane + 32 * t]; int np = lane + 32 * t;
            if (nv > v3) {
                if (nv > v1) {
                    if (nv > v0) { v3=v2;p3=p2; v2=v1;p2=p1; v1=v0;p1=p0; v0=nv;p0=np; }
                    else         { v3=v2;p3=p2; v2=v1;p2=p1; v1=nv;p1=np; }
                } else {
                    if (nv > v2) { v3=v2;p3=p2; v2=nv;p2=np; }
                    else         { v3=nv;p3=np; }
                }
            }
        }
        int cnt = 4;

        unsigned kb = fmono(v0);
        unsigned mk = __reduce_max_sync(0xffffffffu, kb);
        unsigned cp = (kb == mk) ? (unsigned)p0 : 0xffffffffu;
        unsigned bp = __reduce_min_sync(0xffffffffu, cp);
        const float m = fdemono(mk);

        float s0 = 0.f, s1 = 0.f, s2 = 0.f, s3 = 0.f;
#pragma unroll
        for (int t = 0; t < 32; t += 4) {
            s0 += __expf(Sr[lane + 32 * (t + 0)] - m);
            s1 += __expf(Sr[lane + 32 * (t + 1)] - m);
            s2 += __expf(Sr[lane + 32 * (t + 2)] - m);
            s3 += __expf(Sr[lane + 32 * (t + 3)] - m);
        }
        float sum = (s0 + s1) + (s2 + s3);
#pragma unroll
        for (int o = 16; o; o >>= 1) sum += __shfl_xor_sync(~0u, sum, o);
        const float inv = 1.0f / sum;

        if (lane == 0) { tpi[w * TOPK] = (int)bp; tpp[w * TOPK] = inv; }
        if ((bp & 31) == lane) {
            Sr[bp] = -INFINITY;
            v0=v1;p0=p1; v1=v2;p1=p2; v2=v3;p2=p3; v3=-INFINITY;
            if (--cnt == 0) {
                v0=v1=v2=v3=-INFINITY; p0=p1=p2=p3=0;
                for (int t = 0; t < 32; t++) {
                    float nv = Sr[lane + 32 * t]; int np = lane + 32 * t;
                    if (nv > v3) {
                        if (nv > v1) {
                            if (nv > v0) { v3=v2;p3=p2; v2=v1;p2=p1; v1=v0;p1=p0; v0=nv;p0=np; }
                            else         { v3=v2;p3=p2; v2=v1;p2=p1; v1=nv;p1=np; }
                        } else {
                            if (nv > v2) { v3=v2;p3=p2; v2=nv;p2=np; }
                            else         { v3=nv;p3=np; }
                        }
                    }
                }
                cnt = 4;
            }
        }

        for (int it = 1; it < TOPK; it++) {
            kb = fmono(v0);
            mk = __reduce_max_sync(0xffffffffu, kb);
            cp = (kb == mk) ? (unsigned)p0 : 0xffffffffu;
            bp = __reduce_min_sync(0xffffffffu, cp);
            if (lane == 0) {
                tpi[w * TOPK + it] = (int)bp;
                tpp[w * TOPK + it] = __expf(fdemono(mk) - m) * inv;
            }
            if ((bp & 31) == lane) {
                Sr[bp] = -INFINITY;
                v0=v1;p0=p1; v1=v2;p1=p2; v2=v3;p2=p3; v3=-INFINITY;
                if (--cnt == 0) {
                    v0=v1=v2=v3=-INFINITY; p0=p1=p2=p3=0;
                    for (int t = 0; t < 32; t++) {
                        float nv = Sr[lane + 32 * t]; int np = lane + 32 * t;
                        if (nv > v3) {
                            if (nv > v1) {
                                if (nv > v0) { v3=v2;p3=p2; v2=v1;p2=p1; v1=v0;p1=p0; v0=nv;p0=np; }
                                else         { v3=v2;p3=p2; v2=v1;p2=p1; v1=nv;p1=np; }
                            } else {
                                if (nv > v2) { v3=v2;p3=p2; v2=nv;p2=np; }
                                else         { v3=nv;p3=np; }
                            }
                        }
                    }
                    cnt = 4;
                }
            }
        }
    }
    __syncthreads();

    // ---- sparse ctx: 16-key gather; 32 threads x float2 per row ----
    const int cr = tid >> 5;               // 0..15 query row (== w)
    const int d0 = (tid & 31) * 2;
    float c0 = 0.f, c1 = 0.f;
#pragma unroll
    for (int i = 0; i < TOPK; i++) {
        const int   idx = tpi[cr * TOPK + i];
        const float p   = tpp[cr * TOPK + i];
        float2 a = *(const float2*)(vg + (long)idx * BE + base + d0);
        c0 = fmaf(p, a.x, c0); c1 = fmaf(p, a.y, c1);
    }
    *(float2*)(ctxg + (long)(qt * QT + cr) * BE + base + d0) = make_float2(c0, c1);
}

// =====================================================================
// launch
// =====================================================================
static const size_t ATTN_SMEM =
    (size_t)(QT * SP + 2 * KT * 64 + 8 * 64 * 2 + QT * TOPK + QT * TOPK) * 4;

extern "C" void kernel_launch(void* const* d_in, const int* in_sizes, int n_in,
                              void* d_out, int out_size)
{
    const float* query  = (const float*)d_in[0];
    const float* key_in = (const float*)d_in[1];
    const float* value  = (const float*)d_in[2];
    const float* Wq = (const float*)d_in[3];
    const float* bq = (const float*)d_in[4];
    const float* Wk = (const float*)d_in[5];
    const float* bk = (const float*)d_in[6];
    const float* Wv = (const float*)d_in[7];
    const float* bv = (const float*)d_in[8];
    const float* Wo = (const float*)d_in[9];
    const float* bo = (const float*)d_in[10];
    float* out = (float*)d_out;

    float *pq, *pk, *pv, *pctx;
    cudaGetSymbolAddress((void**)&pq,   g_q);
    cudaGetSymbolAddress((void**)&pk,   g_k);
    cudaGetSymbolAddress((void**)&pv,   g_v);
    cudaGetSymbolAddress((void**)&pctx, g_ctx);

    cudaFuncSetAttribute(attn_kernel,
                         cudaFuncAttributeMaxDynamicSharedMemorySize,
                         (int)ATTN_SMEM);

    dim3 gq(ROWS / 128, DIN / 128, 12);
    qkv_gemm<<<gq, 256>>>(query, key_in, value,
                          Wq, bq, Wk, bk, Wv, bv, pq, pk, pv);

    dim3 ag(T_ / QT, B_ * H_);
    attn_kernel<<<ag, NTH, ATTN_SMEM>>>(pq, pk, pv, pctx);

    dim3 go(ROWS / 128, DIN / 128, NB);
    o_gemm<<<go, 256>>>(pctx, Wo, bo, out);
}

// round 9
// speedup vs baseline: 1.0188x; 1.0188x over previous
#include <cuda_runtime.h>
#include <math.h>

#define T_   1024
#define B_   8
#define E_   1024
#define H_   16
#define HD   64
#define NB   4
#define DIN  256
#define TOPK 16
#define ROWS (T_*B_)          // 8192
#define BE   (B_*E_)          // 8192
#define SCALING 0.125f        // 64^-0.5

// ---------- scratch (device globals; no runtime allocation) ----------
__device__ float g_q[ROWS * E_];
__device__ float g_k[ROWS * E_];
__device__ float g_v[ROWS * E_];
__device__ float g_ctx[ROWS * E_];

// ---------- packed f32x2 helpers (exact lane-wise IEEE rn) ----------
__device__ __forceinline__ void dup2(unsigned long long& d, float f) {
    asm("mov.b64 %0, {%1, %1};" : "=l"(d) : "r"(__float_as_uint(f)));
}
__device__ __forceinline__ void fma2(unsigned long long& d,
                                     unsigned long long a,
                                     unsigned long long b,
                                     unsigned long long c) {
    asm("fma.rn.f32x2 %0, %1, %2, %3;" : "=l"(d) : "l"(a), "l"(b), "l"(c));
}
__device__ __forceinline__ void unpack2(float& lo, float& hi, unsigned long long p) {
    unsigned l, h;
    asm("mov.b64 {%0, %1}, %2;" : "=r"(l), "=r"(h) : "l"(p));
    lo = __uint_as_float(l); hi = __uint_as_float(h);
}

// =====================================================================
// Double-buffered block-diagonal GEMM core (BK=16, FFMA2, conflict-free
// B via paired LDS.64) — unchanged from R8 (proven 246us qkv).
// =====================================================================
__device__ __forceinline__ void gemm_core(
    const float* __restrict__ X, const float* __restrict__ W,
    const float* __restrict__ bias, float* __restrict__ Y,
    float scale, int nb)
{
    const int m0 = blockIdx.x * 128;
    const int n0 = blockIdx.y * 128;
    const float* Wn = W + nb * DIN * DIN;

    __shared__ __align__(16) float As[2][16][128];
    __shared__ __align__(16) float Bs[2][16][128];

    const int tid = threadIdx.x;
    const int ty  = tid >> 4;
    const int tx2 = (tid & 15) * 2;
    const int arow = tid >> 1;
    const int akc  = (tid & 1) * 8;
    const int bkr  = tid >> 4;
    const int bcol = (tid & 15) * 8;

    const float* Xb = X + (long)m0 * E_ + nb * DIN;
    const float* Ap = Xb + (long)arow * E_;

    {
        float4 a0 = *(const float4*)(Ap + akc);
        float4 a1 = *(const float4*)(Ap + akc + 4);
        float4 b0 = *(const float4*)(Wn + bkr * DIN + n0 + bcol);
        float4 b1 = *(const float4*)(Wn + bkr * DIN + n0 + bcol + 4);
        As[0][akc+0][arow] = a0.x; As[0][akc+1][arow] = a0.y;
        As[0][akc+2][arow] = a0.z; As[0][akc+3][arow] = a0.w;
        As[0][akc+4][arow] = a1.x; As[0][akc+5][arow] = a1.y;
        As[0][akc+6][arow] = a1.z; As[0][akc+7][arow] = a1.w;
        *(float4*)&Bs[0][bkr][bcol]     = b0;
        *(float4*)&Bs[0][bkr][bcol + 4] = b1;
    }
    __syncthreads();

    unsigned long long accp[8][4];
#pragma unroll
    for (int i = 0; i < 8; i++)
#pragma unroll
        for (int j = 0; j < 4; j++) accp[i][j] = 0ull;

    for (int k0 = 0; k0 < 16; k0++) {
        const int cur = k0 & 1;
        float4 a0, a1, b0, b1;
        if (k0 < 15) {
            const int kn = (k0 + 1) * 16;
            a0 = *(const float4*)(Ap + kn + akc);
            a1 = *(const float4*)(Ap + kn + akc + 4);
            b0 = *(const float4*)(Wn + (kn + bkr) * DIN + n0 + bcol);
            b1 = *(const float4*)(Wn + (kn + bkr) * DIN + n0 + bcol + 4);
        }
#pragma unroll
        for (int kk = 0; kk < 16; kk++) {
            float af[8];
            *(float4*)(af)     = *(const float4*)&As[cur][kk][ty * 8];
            *(float4*)(af + 4) = *(const float4*)&As[cur][kk][ty * 8 + 4];
            unsigned long long bp[4];
#pragma unroll
            for (int j = 0; j < 4; j++)
                bp[j] = *(const unsigned long long*)&Bs[cur][kk][tx2 + 32 * j];
#pragma unroll
            for (int i = 0; i < 8; i++) {
                unsigned long long aa;
                dup2(aa, af[i]);
                fma2(accp[i][0], aa, bp[0], accp[i][0]);
                fma2(accp[i][1], aa, bp[1], accp[i][1]);
                fma2(accp[i][2], aa, bp[2], accp[i][2]);
                fma2(accp[i][3], aa, bp[3], accp[i][3]);
            }
        }
        if (k0 < 15) {
            const int nxt = cur ^ 1;
            As[nxt][akc+0][arow] = a0.x; As[nxt][akc+1][arow] = a0.y;
            As[nxt][akc+2][arow] = a0.z; As[nxt][akc+3][arow] = a0.w;
            As[nxt][akc+4][arow] = a1.x; As[nxt][akc+5][arow] = a1.y;
            As[nxt][akc+6][arow] = a1.z; As[nxt][akc+7][arow] = a1.w;
            *(float4*)&Bs[nxt][bkr][bcol]     = b0;
            *(float4*)&Bs[nxt][bkr][bcol + 4] = b1;
        }
        __syncthreads();
    }

    float2 bj[4];
#pragma unroll
    for (int j = 0; j < 4; j++) {
        bj[j].x = bias[nb * DIN + n0 + tx2 + 32 * j];
        bj[j].y = bias[nb * DIN + n0 + tx2 + 32 * j + 1];
    }

#pragma unroll
    for (int i = 0; i < 8; i++) {
        const long row = m0 + ty * 8 + i;
        float* yp = Y + row * E_ + nb * DIN + n0;
#pragma unroll
        for (int j = 0; j < 4; j++) {
            float lo, hi;
            unpack2(lo, hi, accp[i][j]);
            *(float2*)(yp + tx2 + 32 * j) =
                make_float2((lo + bj[j].x) * scale, (hi + bj[j].y) * scale);
        }
    }
}

__global__ void __launch_bounds__(256) qkv_gemm(
    const float* __restrict__ Q, const float* __restrict__ Kin,
    const float* __restrict__ V,
    const float* __restrict__ Wq, const float* __restrict__ bq,
    const float* __restrict__ Wk, const float* __restrict__ bk,
    const float* __restrict__ Wv, const float* __restrict__ bv,
    float* __restrict__ Yq, float* __restrict__ Yk, float* __restrict__ Yv)
{
    const int op = blockIdx.z >> 2;
    const int nb = blockIdx.z & 3;
    if (op == 0)      gemm_core(Q,   Wq, bq, Yq, SCALING, nb);
    else if (op == 1) gemm_core(Kin, Wk, bk, Yk, 1.0f,    nb);
    else              gemm_core(V,   Wv, bv, Yv, 1.0f,    nb);
}

__global__ void __launch_bounds__(256) o_gemm(
    const float* __restrict__ X, const float* __restrict__ W,
    const float* __restrict__ bias, float* __restrict__ Y)
{
    gemm_core(X, W, bias, Y, 1.0f, blockIdx.z);
}

// =====================================================================
// Fused attention. QT=16, 512 threads, 2 blocks/SM. ALL 16 warps
// compute scores: warp role = (pair-group pg = w>>2: q-pairs 2pg,2pg+1)
// x (key-quarter s = w&3: keys s*32+lane). Same fma2/dup2 chains and
// d-ascending order as R7 -> bitwise-identical scores -> same top-k.
// =====================================================================
#define QT  16
#define KT  128
#define SP  1032
#define NTH 512

__device__ __forceinline__ unsigned fmono(float f) {
    unsigned b = __float_as_uint(f);
    return (b & 0x80000000u) ? ~b : (b | 0x80000000u);
}
__device__ __forceinline__ float fdemono(unsigned m) {
    unsigned b = (m & 0x80000000u) ? (m & 0x7fffffffu) : ~m;
    return __uint_as_float(b);
}

__global__ void __launch_bounds__(NTH, 2) attn_kernel(
    const float* __restrict__ qg, const float* __restrict__ kg,
    const float* __restrict__ vg, float* __restrict__ ctxg)
{
    extern __shared__ float sm[];
    float* S    = sm;                      // QT*SP              (66048 B)
    float* ks   = S + QT * SP;             // 128 x 64 swizzled  (32768 B)
    float* qp   = ks + KT * 64;            // 8 pairs x 64 d x float2 (4096 B)
    float* tpp  = qp + 8 * 64 * 2;         // QT*16
    int*   tpi  = (int*)(tpp + QT * TOPK); // QT*16

    const int tid = threadIdx.x;
    const int qt  = blockIdx.x;            // 0..63
    const int bh  = blockIdx.y;            // 0..127
    const int bb  = bh >> 4;
    const int hh  = bh & 15;
    const long base = (long)bb * E_ + hh * HD;

    const int lane = tid & 31;
    const int w    = tid >> 5;             // warp 0..15

    // ---- build q pairs: qp[pair][d] = {q[2p][d], q[2p+1][d]} ----
    {
        const int p = tid >> 6;            // 0..7
        const int d = tid & 63;
        const float* q0 = qg + (long)(qt * QT + 2 * p) * BE + base + d;
        *(float2*)&qp[(p * 64 + d) * 2] = make_float2(q0[0], q0[BE]);
    }

    // score warp roles: pg = pair group (pairs 2pg, 2pg+1), s = key quarter
    const int pg = w >> 2;                 // 0..3
    const int s  = w & 3;                  // keys s*32 + lane
    const int lane7 = lane & 7;
    const float* ka = ks + (s * 32 + lane) * 64;
    const float* qb = qp + (pg * 2) * 128; // pair stride = 64 d * 2 floats

    for (int kt = 0; kt < T_ / KT; kt++) {
        __syncthreads();
        for (int f = tid; f < KT * 16; f += NTH) {
            int key = f >> 4, d4x = f & 15;
            float4 v4 = *(const float4*)(kg + (long)(kt * KT + key) * BE + base + d4x * 4);
            *(float4*)&ks[key * 64 + ((d4x ^ (key & 7)) << 2)] = v4;
        }
        __syncthreads();

        unsigned long long acc0 = 0ull, acc1 = 0ull;
#pragma unroll
        for (int d4 = 0; d4 < 16; d4++) {
            float4 Kv = *(const float4*)(ka + ((d4 ^ lane7) << 2));
            unsigned long long kd0, kd1, kd2, kd3;
            dup2(kd0, Kv.x); dup2(kd1, Kv.y);
            dup2(kd2, Kv.z); dup2(kd3, Kv.w);

            ulonglong2 qa01 = *(const ulonglong2*)(qb + d4 * 8);
            ulonglong2 qa23 = *(const ulonglong2*)(qb + d4 * 8 + 4);
            fma2(acc0, qa01.x, kd0, acc0);
            fma2(acc0, qa01.y, kd1, acc0);
            fma2(acc0, qa23.x, kd2, acc0);
            fma2(acc0, qa23.y, kd3, acc0);

            ulonglong2 qb01 = *(const ulonglong2*)(qb + 128 + d4 * 8);
            ulonglong2 qb23 = *(const ulonglong2*)(qb + 128 + d4 * 8 + 4);
            fma2(acc1, qb01.x, kd0, acc1);
            fma2(acc1, qb01.y, kd1, acc1);
            fma2(acc1, qb23.x, kd2, acc1);
            fma2(acc1, qb23.y, kd3, acc1);
        }

        const int col = kt * KT + s * 32 + lane;
        float lo, hi;
        unpack2(lo, hi, acc0);
        S[(pg * 4 + 0) * SP + col] = lo;
        S[(pg * 4 + 1) * SP + col] = hi;
        unpack2(lo, hi, acc1);
        S[(pg * 4 + 2) * SP + col] = lo;
        S[(pg * 4 + 3) * SP + col] = hi;
    }
    __syncthreads();

    // ---- per-row top-16 + softmax: warp w owns row w (unchanged) ----
    {
        float* Sr = S + w * SP;

        float v0 = -INFINITY, v1 = -INFINITY, v2 = -INFINITY, v3 = -INFINITY;
        int   p0 = 0, p1 = 0, p2 = 0, p3 = 0;
#pragma unroll 8
        for (int t = 0; t < 32; t++) {
            float nv = Sr[lane + 32 * t]; int np = lane + 32 * t;
            if (nv > v3) {
                if (nv > v1) {
                    if (nv > v0) { v3=v2;p3=p2; v2=v1;p2=p1; v1=v0;p1=p0; v0=nv;p0=np; }
                    else         { v3=v2;p3=p2; v2=v1;p2=p1; v1=nv;p1=np; }
                } else {
                    if (nv > v2) { v3=v2;p3=p2; v2=nv;p2=np; }
                    else         { v3=nv;p3=np; }
                }
            }
        }
        int cnt = 4;

        unsigned kb = fmono(v0);
        unsigned mk = __reduce_max_sync(0xffffffffu, kb);
        unsigned cp = (kb == mk) ? (unsigned)p0 : 0xffffffffu;
        unsigned bp = __reduce_min_sync(0xffffffffu, cp);
        const float m = fdemono(mk);

        float s0 = 0.f, s1 = 0.f, s2 = 0.f, s3 = 0.f;
#pragma unroll
        for (int t = 0; t < 32; t += 4) {
            s0 += __expf(Sr[lane + 32 * (t + 0)] - m);
            s1 += __expf(Sr[lane + 32 * (t + 1)] - m);
            s2 += __expf(Sr[lane + 32 * (t + 2)] - m);
            s3 += __expf(Sr[lane + 32 * (t + 3)] - m);
        }
        float sum = (s0 + s1) + (s2 + s3);
#pragma unroll
        for (int o = 16; o; o >>= 1) sum += __shfl_xor_sync(~0u, sum, o);
        const float inv = 1.0f / sum;

        if (lane == 0) { tpi[w * TOPK] = (int)bp; tpp[w * TOPK] = inv; }
        if ((bp & 31) == lane) {
            Sr[bp] = -INFINITY;
            v0=v1;p0=p1; v1=v2;p1=p2; v2=v3;p2=p3; v3=-INFINITY;
            if (--cnt == 0) {
                v0=v1=v2=v3=-INFINITY; p0=p1=p2=p3=0;
                for (int t = 0; t < 32; t++) {
                    float nv = Sr[lane + 32 * t]; int np = lane + 32 * t;
                    if (nv > v3) {
                        if (nv > v1) {
                            if (nv > v0) { v3=v2;p3=p2; v2=v1;p2=p1; v1=v0;p1=p0; v0=nv;p0=np; }
                            else         { v3=v2;p3=p2; v2=v1;p2=p1; v1=nv;p1=np; }
                        } else {
                            if (nv > v2) { v3=v2;p3=p2; v2=nv;p2=np; }
                            else         { v3=nv;p3=np; }
                        }
                    }
                }
                cnt = 4;
            }
        }

        for (int it = 1; it < TOPK; it++) {
            kb = fmono(v0);
            mk = __reduce_max_sync(0xffffffffu, kb);
            cp = (kb == mk) ? (unsigned)p0 : 0xffffffffu;
            bp = __reduce_min_sync(0xffffffffu, cp);
            if (lane == 0) {
                tpi[w * TOPK + it] = (int)bp;
                tpp[w * TOPK + it] = __expf(fdemono(mk) - m) * inv;
            }
            if ((bp & 31) == lane) {
                Sr[bp] = -INFINITY;
                v0=v1;p0=p1; v1=v2;p1=p2; v2=v3;p2=p3; v3=-INFINITY;
                if (--cnt == 0) {
                    v0=v1=v2=v3=-INFINITY; p0=p1=p2=p3=0;
                    for (int t = 0; t < 32; t++) {
                        float nv = Sr[lane + 32 * t]; int np = lane + 32 * t;
                        if (nv > v3) {
                            if (nv > v1) {
                                if (nv > v0) { v3=v2;p3=p2; v2=v1;p2=p1; v1=v0;p1=p0; v0=nv;p0=np; }
                                else         { v3=v2;p3=p2; v2=v1;p2=p1; v1=nv;p1=np; }
                            } else {
                                if (nv > v2) { v3=v2;p3=p2; v2=nv;p2=np; }
                                else         { v3=nv;p3=np; }
                            }
                        }
                    }
                    cnt = 4;
                }
            }
        }
    }
    __syncthreads();

    // ---- sparse ctx: 16-key gather; 32 threads x float2 per row ----
    const int cr = tid >> 5;
    const int d0 = (tid & 31) * 2;
    float c0 = 0.f, c1 = 0.f;
#pragma unroll
    for (int i = 0; i < TOPK; i++) {
        const int   idx = tpi[cr * TOPK + i];
        const float p   = tpp[cr * TOPK + i];
        float2 a = *(const float2*)(vg + (long)idx * BE + base + d0);
        c0 = fmaf(p, a.x, c0); c1 = fmaf(p, a.y, c1);
    }
    *(float2*)(ctxg + (long)(qt * QT + cr) * BE + base + d0) = make_float2(c0, c1);
}

// =====================================================================
// launch
// =====================================================================
static const size_t ATTN_SMEM =
    (size_t)(QT * SP + KT * 64 + 8 * 64 * 2 + QT * TOPK + QT * TOPK) * 4;

extern "C" void kernel_launch(void* const* d_in, const int* in_sizes, int n_in,
                              void* d_out, int out_size)
{
    const float* query  = (const float*)d_in[0];
    const float* key_in = (const float*)d_in[1];
    const float* value  = (const float*)d_in[2];
    const float* Wq = (const float*)d_in[3];
    const float* bq = (const float*)d_in[4];
    const float* Wk = (const float*)d_in[5];
    const float* bk = (const float*)d_in[6];
    const float* Wv = (const float*)d_in[7];
    const float* bv = (const float*)d_in[8];
    const float* Wo = (const float*)d_in[9];
    const float* bo = (const float*)d_in[10];
    float* out = (float*)d_out;

    float *pq, *pk, *pv, *pctx;
    cudaGetSymbolAddress((void**)&pq,   g_q);
    cudaGetSymbolAddress((void**)&pk,   g_k);
    cudaGetSymbolAddress((void**)&pv,   g_v);
    cudaGetSymbolAddress((void**)&pctx, g_ctx);

    cudaFuncSetAttribute(attn_kernel,
                         cudaFuncAttributeMaxDynamicSharedMemorySize,
                         (int)ATTN_SMEM);

    dim3 gq(ROWS / 128, DIN / 128, 12);
    qkv_gemm<<<gq, 256>>>(query, key_in, value,
                          Wq, bq, Wk, bk, Wv, bv, pq, pk, pv);

    dim3 ag(T_ / QT, B_ * H_);
    attn_kernel<<<ag, NTH, ATTN_SMEM>>>(pq, pk, pv, pctx);

    dim3 go(ROWS / 128, DIN / 128, NB);
    o_gemm<<<go, 256>>>(pctx, Wo, bo, out);
}

// round 10
// speedup vs baseline: 1.1505x; 1.1292x over previous
#include <cuda_runtime.h>
#include <math.h>

#define T_   1024
#define B_   8
#define E_   1024
#define H_   16
#define HD   64
#define NB   4
#define DIN  256
#define TOPK 16
#define ROWS (T_*B_)          // 8192
#define BE   (B_*E_)          // 8192
#define SCALING 0.125f        // 64^-0.5

// ---------- scratch (device globals; no runtime allocation) ----------
__device__ float g_q[ROWS * E_];
__device__ float g_k[ROWS * E_];
__device__ float g_v[ROWS * E_];
__device__ float g_ctx[ROWS * E_];

// ---------- packed f32x2 helpers (exact lane-wise IEEE rn) ----------
__device__ __forceinline__ void dup2(unsigned long long& d, float f) {
    asm("mov.b64 %0, {%1, %1};" : "=l"(d) : "r"(__float_as_uint(f)));
}
__device__ __forceinline__ void fma2(unsigned long long& d,
                                     unsigned long long a,
                                     unsigned long long b,
                                     unsigned long long c) {
    asm("fma.rn.f32x2 %0, %1, %2, %3;" : "=l"(d) : "l"(a), "l"(b), "l"(c));
}
__device__ __forceinline__ void unpack2(float& lo, float& hi, unsigned long long p) {
    unsigned l, h;
    asm("mov.b64 {%0, %1}, %2;" : "=r"(l), "=r"(h) : "l"(p));
    lo = __uint_as_float(l); hi = __uint_as_float(h);
}

// =====================================================================
// Double-buffered block-diagonal GEMM core (BK=16, FFMA2, conflict-free
// B via paired LDS.64) — unchanged from R8/R9 (proven 245us qkv).
// =====================================================================
__device__ __forceinline__ void gemm_core(
    const float* __restrict__ X, const float* __restrict__ W,
    const float* __restrict__ bias, float* __restrict__ Y,
    float scale, int nb)
{
    const int m0 = blockIdx.x * 128;
    const int n0 = blockIdx.y * 128;
    const float* Wn = W + nb * DIN * DIN;

    __shared__ __align__(16) float As[2][16][128];
    __shared__ __align__(16) float Bs[2][16][128];

    const int tid = threadIdx.x;
    const int ty  = tid >> 4;
    const int tx2 = (tid & 15) * 2;
    const int arow = tid >> 1;
    const int akc  = (tid & 1) * 8;
    const int bkr  = tid >> 4;
    const int bcol = (tid & 15) * 8;

    const float* Xb = X + (long)m0 * E_ + nb * DIN;
    const float* Ap = Xb + (long)arow * E_;

    {
        float4 a0 = *(const float4*)(Ap + akc);
        float4 a1 = *(const float4*)(Ap + akc + 4);
        float4 b0 = *(const float4*)(Wn + bkr * DIN + n0 + bcol);
        float4 b1 = *(const float4*)(Wn + bkr * DIN + n0 + bcol + 4);
        As[0][akc+0][arow] = a0.x; As[0][akc+1][arow] = a0.y;
        As[0][akc+2][arow] = a0.z; As[0][akc+3][arow] = a0.w;
        As[0][akc+4][arow] = a1.x; As[0][akc+5][arow] = a1.y;
        As[0][akc+6][arow] = a1.z; As[0][akc+7][arow] = a1.w;
        *(float4*)&Bs[0][bkr][bcol]     = b0;
        *(float4*)&Bs[0][bkr][bcol + 4] = b1;
    }
    __syncthreads();

    unsigned long long accp[8][4];
#pragma unroll
    for (int i = 0; i < 8; i++)
#pragma unroll
        for (int j = 0; j < 4; j++) accp[i][j] = 0ull;

    for (int k0 = 0; k0 < 16; k0++) {
        const int cur = k0 & 1;
        float4 a0, a1, b0, b1;
        if (k0 < 15) {
            const int kn = (k0 + 1) * 16;
            a0 = *(const float4*)(Ap + kn + akc);
            a1 = *(const float4*)(Ap + kn + akc + 4);
            b0 = *(const float4*)(Wn + (kn + bkr) * DIN + n0 + bcol);
            b1 = *(const float4*)(Wn + (kn + bkr) * DIN + n0 + bcol + 4);
        }
#pragma unroll
        for (int kk = 0; kk < 16; kk++) {
            float af[8];
            *(float4*)(af)     = *(const float4*)&As[cur][kk][ty * 8];
            *(float4*)(af + 4) = *(const float4*)&As[cur][kk][ty * 8 + 4];
            unsigned long long bp[4];
#pragma unroll
            for (int j = 0; j < 4; j++)
                bp[j] = *(const unsigned long long*)&Bs[cur][kk][tx2 + 32 * j];
#pragma unroll
            for (int i = 0; i < 8; i++) {
                unsigned long long aa;
                dup2(aa, af[i]);
                fma2(accp[i][0], aa, bp[0], accp[i][0]);
                fma2(accp[i][1], aa, bp[1], accp[i][1]);
                fma2(accp[i][2], aa, bp[2], accp[i][2]);
                fma2(accp[i][3], aa, bp[3], accp[i][3]);
            }
        }
        if (k0 < 15) {
            const int nxt = cur ^ 1;
            As[nxt][akc+0][arow] = a0.x; As[nxt][akc+1][arow] = a0.y;
            As[nxt][akc+2][arow] = a0.z; As[nxt][akc+3][arow] = a0.w;
            As[nxt][akc+4][arow] = a1.x; As[nxt][akc+5][arow] = a1.y;
            As[nxt][akc+6][arow] = a1.z; As[nxt][akc+7][arow] = a1.w;
            *(float4*)&Bs[nxt][bkr][bcol]     = b0;
            *(float4*)&Bs[nxt][bkr][bcol + 4] = b1;
        }
        __syncthreads();
    }

    float2 bj[4];
#pragma unroll
    for (int j = 0; j < 4; j++) {
        bj[j].x = bias[nb * DIN + n0 + tx2 + 32 * j];
        bj[j].y = bias[nb * DIN + n0 + tx2 + 32 * j + 1];
    }

#pragma unroll
    for (int i = 0; i < 8; i++) {
        const long row = m0 + ty * 8 + i;
        float* yp = Y + row * E_ + nb * DIN + n0;
#pragma unroll
        for (int j = 0; j < 4; j++) {
            float lo, hi;
            unpack2(lo, hi, accp[i][j]);
            *(float2*)(yp + tx2 + 32 * j) =
                make_float2((lo + bj[j].x) * scale, (hi + bj[j].y) * scale);
        }
    }
}

__global__ void __launch_bounds__(256) qkv_gemm(
    const float* __restrict__ Q, const float* __restrict__ Kin,
    const float* __restrict__ V,
    const float* __restrict__ Wq, const float* __restrict__ bq,
    const float* __restrict__ Wk, const float* __restrict__ bk,
    const float* __restrict__ Wv, const float* __restrict__ bv,
    float* __restrict__ Yq, float* __restrict__ Yk, float* __restrict__ Yv)
{
    const int op = blockIdx.z >> 2;
    const int nb = blockIdx.z & 3;
    if (op == 0)      gemm_core(Q,   Wq, bq, Yq, SCALING, nb);
    else if (op == 1) gemm_core(Kin, Wk, bk, Yk, 1.0f,    nb);
    else              gemm_core(V,   Wv, bv, Yv, 1.0f,    nb);
}

__global__ void __launch_bounds__(256) o_gemm(
    const float* __restrict__ X, const float* __restrict__ W,
    const float* __restrict__ bias, float* __restrict__ Y)
{
    gemm_core(X, W, bias, Y, 1.0f, blockIdx.z);
}

// =====================================================================
// Fused attention — R7 structure (best measured): QT=16, 512 threads,
// 2 blocks/SM, all-thread tile loader, 4 score warps of 4 q-pairs x
// 64 keys. CHANGE vs R7: q broadcasts via 2x LDS.128 instead of
// 4x LDS.64 per (d4,dd) — halves q wavefronts; operands and per-chain
// fma2 order unchanged -> scores bitwise identical -> same top-k.
// =====================================================================
#define QT  16
#define KT  128
#define SP  1032
#define NTH 512

__device__ __forceinline__ unsigned fmono(float f) {
    unsigned b = __float_as_uint(f);
    return (b & 0x80000000u) ? ~b : (b | 0x80000000u);
}
__device__ __forceinline__ float fdemono(unsigned m) {
    unsigned b = (m & 0x80000000u) ? (m & 0x7fffffffu) : ~m;
    return __uint_as_float(b);
}

__global__ void __launch_bounds__(NTH, 2) attn_kernel(
    const float* __restrict__ qg, const float* __restrict__ kg,
    const float* __restrict__ vg, float* __restrict__ ctxg)
{
    extern __shared__ float sm[];
    float* S    = sm;                      // QT*SP              (66048 B)
    float* ks   = S + QT * SP;             // 128 x 64 swizzled  (32768 B)
    float* qp   = ks + KT * 64;            // [d][pair] 64 x 8 x float2 (4096 B)
    float* tpp  = qp + 64 * 8 * 2;         // QT*16
    int*   tpi  = (int*)(tpp + QT * TOPK); // QT*16

    const int tid = threadIdx.x;
    const int qt  = blockIdx.x;            // 0..63
    const int bh  = blockIdx.y;            // 0..127
    const int bb  = bh >> 4;
    const int hh  = bh & 15;
    const long base = (long)bb * E_ + hh * HD;

    const int lane = tid & 31;
    const int w    = tid >> 5;             // warp 0..15

    // ---- build q pairs: qp[(d*8+p)*2] = {q[2p][d], q[2p+1][d]} ----
    {
        const int p = tid >> 6;            // 0..7
        const int d = tid & 63;
        const float* q0 = qg + (long)(qt * QT + 2 * p) * BE + base + d;
        *(float2*)&qp[(d * 8 + p) * 2] = make_float2(q0[0], q0[BE]);
    }

    // score warp roles (w<4): g = pair group (pairs g*4..g*4+3), s = key half
    const int g = (w >> 1) & 1;
    const int s = w & 1;
    const int lane7 = lane & 7;
    const float* ka_ptr = ks + (s * 64 + lane) * 64;
    const float* kb_ptr = ka_ptr + 32 * 64;

    for (int kt = 0; kt < T_ / KT; kt++) {
        __syncthreads();
        for (int f = tid; f < KT * 16; f += NTH) {
            int key = f >> 4, d4x = f & 15;
            float4 v4 = *(const float4*)(kg + (long)(kt * KT + key) * BE + base + d4x * 4);
            *(float4*)&ks[key * 64 + ((d4x ^ (key & 7)) << 2)] = v4;
        }
        __syncthreads();

        if (w < 4) {
            unsigned long long acc[4][2];
#pragma unroll
            for (int p = 0; p < 4; p++) { acc[p][0] = 0ull; acc[p][1] = 0ull; }

#pragma unroll 4
            for (int d4 = 0; d4 < 16; d4++) {
                const int c = (d4 ^ lane7) << 2;
                float4 Ka = *(const float4*)(ka_ptr + c);
                float4 Kb = *(const float4*)(kb_ptr + c);
#pragma unroll
                for (int dd = 0; dd < 4; dd++) {
                    unsigned long long kda, kdb;
                    dup2(kda, (&Ka.x)[dd]);
                    dup2(kdb, (&Kb.x)[dd]);
                    const float* qpd = qp + (((d4 * 4 + dd) * 8) + g * 4) * 2;
                    ulonglong2 q01 = *(const ulonglong2*)(qpd);
                    ulonglong2 q23 = *(const ulonglong2*)(qpd + 4);
                    fma2(acc[0][0], q01.x, kda, acc[0][0]);
                    fma2(acc[0][1], q01.x, kdb, acc[0][1]);
                    fma2(acc[1][0], q01.y, kda, acc[1][0]);
                    fma2(acc[1][1], q01.y, kdb, acc[1][1]);
                    fma2(acc[2][0], q23.x, kda, acc[2][0]);
                    fma2(acc[2][1], q23.x, kdb, acc[2][1]);
                    fma2(acc[3][0], q23.y, kda, acc[3][0]);
                    fma2(acc[3][1], q23.y, kdb, acc[3][1]);
                }
            }

            const int col = kt * KT + s * 64 + lane;
#pragma unroll
            for (int p = 0; p < 4; p++) {
                float lo, hi;
                unpack2(lo, hi, acc[p][0]);
                S[(g * 8 + 2 * p    ) * SP + col] = lo;
                S[(g * 8 + 2 * p + 1) * SP + col] = hi;
                unpack2(lo, hi, acc[p][1]);
                S[(g * 8 + 2 * p    ) * SP + col + 32] = lo;
                S[(g * 8 + 2 * p + 1) * SP + col + 32] = hi;
            }
        }
    }
    __syncthreads();

    // ---- per-row top-16 + softmax: warp w owns row w (unchanged) ----
    {
        float* Sr = S + w * SP;

        float v0 = -INFINITY, v1 = -INFINITY, v2 = -INFINITY, v3 = -INFINITY;
        int   p0 = 0, p1 = 0, p2 = 0, p3 = 0;
#pragma unroll 8
        for (int t = 0; t < 32; t++) {
            float nv = Sr[lane + 32 * t]; int np = lane + 32 * t;
            if (nv > v3) {
                if (nv > v1) {
                    if (nv > v0) { v3=v2;p3=p2; v2=v1;p2=p1; v1=v0;p1=p0; v0=nv;p0=np; }
                    else         { v3=v2;p3=p2; v2=v1;p2=p1; v1=nv;p1=np; }
                } else {
                    if (nv > v2) { v3=v2;p3=p2; v2=nv;p2=np; }
                    else         { v3=nv;p3=np; }
                }
            }
        }
        int cnt = 4;

        unsigned kb = fmono(v0);
        unsigned mk = __reduce_max_sync(0xffffffffu, kb);
        unsigned cp = (kb == mk) ? (unsigned)p0 : 0xffffffffu;
        unsigned bp = __reduce_min_sync(0xffffffffu, cp);
        const float m = fdemono(mk);

        float s0 = 0.f, s1 = 0.f, s2 = 0.f, s3 = 0.f;
#pragma unroll
        for (int t = 0; t < 32; t += 4) {
            s0 += __expf(Sr[lane + 32 * (t + 0)] - m);
            s1 += __expf(Sr[lane + 32 * (t + 1)] - m);
            s2 += __expf(Sr[lane + 32 * (t + 2)] - m);
            s3 += __expf(Sr[lane + 32 * (t + 3)] - m);
        }
        float sum = (s0 + s1) + (s2 + s3);
#pragma unroll
        for (int o = 16; o; o >>= 1) sum += __shfl_xor_sync(~0u, sum, o);
        const float inv = 1.0f / sum;

        if (lane == 0) { tpi[w * TOPK] = (int)bp; tpp[w * TOPK] = inv; }
        if ((bp & 31) == lane) {
            Sr[bp] = -INFINITY;
            v0=v1;p0=p1; v1=v2;p1=p2; v2=v3;p2=p3; v3=-INFINITY;
            if (--cnt == 0) {
                v0=v1=v2=v3=-INFINITY; p0=p1=p2=p3=0;
                for (int t = 0; t < 32; t++) {
                    float nv = Sr[lane + 32 * t]; int np = lane + 32 * t;
                    if (nv > v3) {
                        if (nv > v1) {
                            if (nv > v0) { v3=v2;p3=p2; v2=v1;p2=p1; v1=v0;p1=p0; v0=nv;p0=np; }
                            else         { v3=v2;p3=p2; v2=v1;p2=p1; v1=nv;p1=np; }
                        } else {
                            if (nv > v2) { v3=v2;p3=p2; v2=nv;p2=np; }
                            else         { v3=nv;p3=np; }
                        }
                    }
                }
                cnt = 4;
            }
        }

        for (int it = 1; it < TOPK; it++) {
            kb = fmono(v0);
            mk = __reduce_max_sync(0xffffffffu, kb);
            cp = (kb == mk) ? (unsigned)p0 : 0xffffffffu;
            bp = __reduce_min_sync(0xffffffffu, cp);
            if (lane == 0) {
                tpi[w * TOPK + it] = (int)bp;
                tpp[w * TOPK + it] = __expf(fdemono(mk) - m) * inv;
            }
            if ((bp & 31) == lane) {
                Sr[bp] = -INFINITY;
                v0=v1;p0=p1; v1=v2;p1=p2; v2=v3;p2=p3; v3=-INFINITY;
                if (--cnt == 0) {
                    v0=v1=v2=v3=-INFINITY; p0=p1=p2=p3=0;
                    for (int t = 0; t < 32; t++) {
                        float nv = Sr[lane + 32 * t]; int np = lane + 32 * t;
                        if (nv > v3) {
                            if (nv > v1) {
                                if (nv > v0) { v3=v2;p3=p2; v2=v1;p2=p1; v1=v0;p1=p0; v0=nv;p0=np; }
                                else         { v3=v2;p3=p2; v2=v1;p2=p1; v1=nv;p1=np; }
                            } else {
                                if (nv > v2) { v3=v2;p3=p2; v2=nv;p2=np; }
                                else         { v3=nv;p3=np; }
                            }
                        }
                    }
                    cnt = 4;
                }
            }
        }
    }
    __syncthreads();

    // ---- sparse ctx: 16-key gather; 32 threads x float2 per row ----
    const int cr = tid >> 5;
    const int d0 = (tid & 31) * 2;
    float c0 = 0.f, c1 = 0.f;
#pragma unroll
    for (int i = 0; i < TOPK; i++) {
        const int   idx = tpi[cr * TOPK + i];
        const float p   = tpp[cr * TOPK + i];
        float2 a = *(const float2*)(vg + (long)idx * BE + base + d0);
        c0 = fmaf(p, a.x, c0); c1 = fmaf(p, a.y, c1);
    }
    *(float2*)(ctxg + (long)(qt * QT + cr) * BE + base + d0) = make_float2(c0, c1);
}

// =====================================================================
// launch
// =====================================================================
static const size_t ATTN_SMEM =
    (size_t)(QT * SP + KT * 64 + 64 * 8 * 2 + QT * TOPK + QT * TOPK) * 4;

extern "C" void kernel_launch(void* const* d_in, const int* in_sizes, int n_in,
                              void* d_out, int out_size)
{
    const float* query  = (const float*)d_in[0];
    const float* key_in = (const float*)d_in[1];
    const float* value  = (const float*)d_in[2];
    const float* Wq = (const float*)d_in[3];
    const float* bq = (const float*)d_in[4];
    const float* Wk = (const float*)d_in[5];
    const float* bk = (const float*)d_in[6];
    const float* Wv = (const float*)d_in[7];
    const float* bv = (const float*)d_in[8];
    const float* Wo = (const float*)d_in[9];
    const float* bo = (const float*)d_in[10];
    float* out = (float*)d_out;

    float *pq, *pk, *pv, *pctx;
    cudaGetSymbolAddress((void**)&pq,   g_q);
    cudaGetSymbolAddress((void**)&pk,   g_k);
    cudaGetSymbolAddress((void**)&pv,   g_v);
    cudaGetSymbolAddress((void**)&pctx, g_ctx);

    cudaFuncSetAttribute(attn_kernel,
                         cudaFuncAttributeMaxDynamicSharedMemorySize,
                         (int)ATTN_SMEM);

    dim3 gq(ROWS / 128, DIN / 128, 12);
    qkv_gemm<<<gq, 256>>>(query, key_in, value,
                          Wq, bq, Wk, bk, Wv, bv, pq, pk, pv);

    dim3 ag(T_ / QT, B_ * H_);
    attn_kernel<<<ag, NTH, ATTN_SMEM>>>(pq, pk, pv, pctx);

    dim3 go(ROWS / 128, DIN / 128, NB);
    o_gemm<<<go, 256>>>(pctx, Wo, bo, out);
}

// round 11
// speedup vs baseline: 1.1518x; 1.0012x over previous
#include <cuda_runtime.h>
#include <math.h>

#define T_   1024
#define B_   8
#define E_   1024
#define H_   16
#define HD   64
#define NB   4
#define DIN  256
#define TOPK 16
#define ROWS (T_*B_)          // 8192
#define BE   (B_*E_)          // 8192
#define SCALING 0.125f        // 64^-0.5

// ---------- scratch (device globals; no runtime allocation) ----------
__device__ float g_q[ROWS * E_];
__device__ float g_k[ROWS * E_];
__device__ float g_v[ROWS * E_];
__device__ float g_ctx[ROWS * E_];

// ---------- packed f32x2 helpers (exact lane-wise IEEE rn) ----------
__device__ __forceinline__ void dup2(unsigned long long& d, float f) {
    asm("mov.b64 %0, {%1, %1};" : "=l"(d) : "r"(__float_as_uint(f)));
}
__device__ __forceinline__ void fma2(unsigned long long& d,
                                     unsigned long long a,
                                     unsigned long long b,
                                     unsigned long long c) {
    asm("fma.rn.f32x2 %0, %1, %2, %3;" : "=l"(d) : "l"(a), "l"(b), "l"(c));
}
__device__ __forceinline__ void unpack2(float& lo, float& hi, unsigned long long p) {
    unsigned l, h;
    asm("mov.b64 {%0, %1}, %2;" : "=r"(l), "=r"(h) : "l"(p));
    lo = __uint_as_float(l); hi = __uint_as_float(h);
}

// =====================================================================
// Double-buffered block-diagonal GEMM core (BK=16, FFMA2, conflict-free
// B via paired LDS.64) — unchanged (proven 245us qkv).
// =====================================================================
__device__ __forceinline__ void gemm_core(
    const float* __restrict__ X, const float* __restrict__ W,
    const float* __restrict__ bias, float* __restrict__ Y,
    float scale, int nb)
{
    const int m0 = blockIdx.x * 128;
    const int n0 = blockIdx.y * 128;
    const float* Wn = W + nb * DIN * DIN;

    __shared__ __align__(16) float As[2][16][128];
    __shared__ __align__(16) float Bs[2][16][128];

    const int tid = threadIdx.x;
    const int ty  = tid >> 4;
    const int tx2 = (tid & 15) * 2;
    const int arow = tid >> 1;
    const int akc  = (tid & 1) * 8;
    const int bkr  = tid >> 4;
    const int bcol = (tid & 15) * 8;

    const float* Xb = X + (long)m0 * E_ + nb * DIN;
    const float* Ap = Xb + (long)arow * E_;

    {
        float4 a0 = *(const float4*)(Ap + akc);
        float4 a1 = *(const float4*)(Ap + akc + 4);
        float4 b0 = *(const float4*)(Wn + bkr * DIN + n0 + bcol);
        float4 b1 = *(const float4*)(Wn + bkr * DIN + n0 + bcol + 4);
        As[0][akc+0][arow] = a0.x; As[0][akc+1][arow] = a0.y;
        As[0][akc+2][arow] = a0.z; As[0][akc+3][arow] = a0.w;
        As[0][akc+4][arow] = a1.x; As[0][akc+5][arow] = a1.y;
        As[0][akc+6][arow] = a1.z; As[0][akc+7][arow] = a1.w;
        *(float4*)&Bs[0][bkr][bcol]     = b0;
        *(float4*)&Bs[0][bkr][bcol + 4] = b1;
    }
    __syncthreads();

    unsigned long long accp[8][4];
#pragma unroll
    for (int i = 0; i < 8; i++)
#pragma unroll
        for (int j = 0; j < 4; j++) accp[i][j] = 0ull;

    for (int k0 = 0; k0 < 16; k0++) {
        const int cur = k0 & 1;
        float4 a0, a1, b0, b1;
        if (k0 < 15) {
            const int kn = (k0 + 1) * 16;
            a0 = *(const float4*)(Ap + kn + akc);
            a1 = *(const float4*)(Ap + kn + akc + 4);
            b0 = *(const float4*)(Wn + (kn + bkr) * DIN + n0 + bcol);
            b1 = *(const float4*)(Wn + (kn + bkr) * DIN + n0 + bcol + 4);
        }
#pragma unroll
        for (int kk = 0; kk < 16; kk++) {
            float af[8];
            *(float4*)(af)     = *(const float4*)&As[cur][kk][ty * 8];
            *(float4*)(af + 4) = *(const float4*)&As[cur][kk][ty * 8 + 4];
            unsigned long long bp[4];
#pragma unroll
            for (int j = 0; j < 4; j++)
                bp[j] = *(const unsigned long long*)&Bs[cur][kk][tx2 + 32 * j];
#pragma unroll
            for (int i = 0; i < 8; i++) {
                unsigned long long aa;
                dup2(aa, af[i]);
                fma2(accp[i][0], aa, bp[0], accp[i][0]);
                fma2(accp[i][1], aa, bp[1], accp[i][1]);
                fma2(accp[i][2], aa, bp[2], accp[i][2]);
                fma2(accp[i][3], aa, bp[3], accp[i][3]);
            }
        }
        if (k0 < 15) {
            const int nxt = cur ^ 1;
            As[nxt][akc+0][arow] = a0.x; As[nxt][akc+1][arow] = a0.y;
            As[nxt][akc+2][arow] = a0.z; As[nxt][akc+3][arow] = a0.w;
            As[nxt][akc+4][arow] = a1.x; As[nxt][akc+5][arow] = a1.y;
            As[nxt][akc+6][arow] = a1.z; As[nxt][akc+7][arow] = a1.w;
            *(float4*)&Bs[nxt][bkr][bcol]     = b0;
            *(float4*)&Bs[nxt][bkr][bcol + 4] = b1;
        }
        __syncthreads();
    }

    float2 bj[4];
#pragma unroll
    for (int j = 0; j < 4; j++) {
        bj[j].x = bias[nb * DIN + n0 + tx2 + 32 * j];
        bj[j].y = bias[nb * DIN + n0 + tx2 + 32 * j + 1];
    }

#pragma unroll
    for (int i = 0; i < 8; i++) {
        const long row = m0 + ty * 8 + i;
        float* yp = Y + row * E_ + nb * DIN + n0;
#pragma unroll
        for (int j = 0; j < 4; j++) {
            float lo, hi;
            unpack2(lo, hi, accp[i][j]);
            *(float2*)(yp + tx2 + 32 * j) =
                make_float2((lo + bj[j].x) * scale, (hi + bj[j].y) * scale);
        }
    }
}

__global__ void __launch_bounds__(256) qkv_gemm(
    const float* __restrict__ Q, const float* __restrict__ Kin,
    const float* __restrict__ V,
    const float* __restrict__ Wq, const float* __restrict__ bq,
    const float* __restrict__ Wk, const float* __restrict__ bk,
    const float* __restrict__ Wv, const float* __restrict__ bv,
    float* __restrict__ Yq, float* __restrict__ Yk, float* __restrict__ Yv)
{
    const int op = blockIdx.z >> 2;
    const int nb = blockIdx.z & 3;
    if (op == 0)      gemm_core(Q,   Wq, bq, Yq, SCALING, nb);
    else if (op == 1) gemm_core(Kin, Wk, bk, Yk, 1.0f,    nb);
    else              gemm_core(V,   Wv, bv, Yv, 1.0f,    nb);
}

__global__ void __launch_bounds__(256) o_gemm(
    const float* __restrict__ X, const float* __restrict__ W,
    const float* __restrict__ bias, float* __restrict__ Y)
{
    gemm_core(X, W, bias, Y, 1.0f, blockIdx.z);
}

// =====================================================================
// Fused attention — R10 score config (proven), with:
//  * register-prefetch of next K tile (LDG hidden behind scoring)
//  * top-k: contiguous per-lane ownership (8x LDS.128 scans) and
//    branchless top-4 insertion. Selection semantics identical
//    (global max, min-pos tie-break is partition-independent); sum
//    pass keeps old indexing -> bitwise-identical denominators.
// =====================================================================
#define QT  16
#define KT  128
#define SP  1032
#define NTH 512

__device__ __forceinline__ unsigned fmono(float f) {
    unsigned b = __float_as_uint(f);
    return (b & 0x80000000u) ? ~b : (b | 0x80000000u);
}
__device__ __forceinline__ float fdemono(unsigned m) {
    unsigned b = (m & 0x80000000u) ? (m & 0x7fffffffu) : ~m;
    return __uint_as_float(b);
}

// branchless sorted-top4 insertion; strict > keeps earliest pos on ties
#define INS4(nv, np)                                                   \
    do {                                                               \
        bool c0 = (nv) > v0, c1 = (nv) > v1,                           \
             c2 = (nv) > v2, c3 = (nv) > v3;                           \
        v3 = c3 ? (c2 ? v2 : (nv)) : v3;                               \
        p3 = c3 ? (c2 ? p2 : (np)) : p3;                               \
        v2 = c2 ? (c1 ? v1 : (nv)) : v2;                               \
        p2 = c2 ? (c1 ? p1 : (np)) : p2;                               \
        v1 = c1 ? (c0 ? v0 : (nv)) : v1;                               \
        p1 = c1 ? (c0 ? p0 : (np)) : p1;                               \
        v0 = c0 ? (nv) : v0;                                           \
        p0 = c0 ? (np) : p0;                                           \
    } while (0)

__global__ void __launch_bounds__(NTH, 2) attn_kernel(
    const float* __restrict__ qg, const float* __restrict__ kg,
    const float* __restrict__ vg, float* __restrict__ ctxg)
{
    extern __shared__ float sm[];
    float* S    = sm;                      // QT*SP              (66048 B)
    float* ks   = S + QT * SP;             // 128 x 64 swizzled  (32768 B)
    float* qp   = ks + KT * 64;            // [d][pair] 64 x 8 x float2 (4096 B)
    float* tpp  = qp + 64 * 8 * 2;         // QT*16
    int*   tpi  = (int*)(tpp + QT * TOPK); // QT*16

    const int tid = threadIdx.x;
    const int qt  = blockIdx.x;            // 0..63
    const int bh  = blockIdx.y;            // 0..127
    const int bb  = bh >> 4;
    const int hh  = bh & 15;
    const long base = (long)bb * E_ + hh * HD;

    const int lane = tid & 31;
    const int w    = tid >> 5;             // warp 0..15

    // ---- build q pairs: qp[(d*8+p)*2] = {q[2p][d], q[2p+1][d]} ----
    {
        const int p = tid >> 6;            // 0..7
        const int d = tid & 63;
        const float* q0 = qg + (long)(qt * QT + 2 * p) * BE + base + d;
        *(float2*)&qp[(d * 8 + p) * 2] = make_float2(q0[0], q0[BE]);
    }

    // loader indices (each thread owns 4 float4 per tile)
    const int lkey = tid >> 4;             // 0..31 (key block row per u)
    const int ld4  = tid & 15;             // chunk
    const int lsw  = (ld4 ^ (lkey & 7)) << 2;

    // ---- prologue: load tile 0 into regs, store, sync ----
    float4 r0_, r1_, r2_, r3_;
    {
        const float* kg0 = kg + base + ld4 * 4;
        r0_ = *(const float4*)(kg0 + (long)(lkey      ) * BE);
        r1_ = *(const float4*)(kg0 + (long)(lkey + 32 ) * BE);
        r2_ = *(const float4*)(kg0 + (long)(lkey + 64 ) * BE);
        r3_ = *(const float4*)(kg0 + (long)(lkey + 96 ) * BE);
        *(float4*)&ks[(lkey      ) * 64 + lsw] = r0_;
        *(float4*)&ks[(lkey + 32 ) * 64 + ((ld4 ^ ((lkey+32) & 7)) << 2)] = r1_;
        *(float4*)&ks[(lkey + 64 ) * 64 + ((ld4 ^ ((lkey+64) & 7)) << 2)] = r2_;
        *(float4*)&ks[(lkey + 96 ) * 64 + ((ld4 ^ ((lkey+96) & 7)) << 2)] = r3_;
    }
    __syncthreads();

    // score warp roles (w<4): g = pair group (pairs g*4..g*4+3), s = key half
    const int g = (w >> 1) & 1;
    const int s = w & 1;
    const int lane7 = lane & 7;
    const float* ka_ptr = ks + (s * 64 + lane) * 64;
    const float* kb_ptr = ka_ptr + 32 * 64;

    for (int kt = 0; kt < T_ / KT; kt++) {
        // prefetch next tile into registers (hidden behind scoring)
        if (kt < T_ / KT - 1) {
            const float* kgn = kg + (long)(kt + 1) * KT * BE + base + ld4 * 4;
            r0_ = *(const float4*)(kgn + (long)(lkey      ) * BE);
            r1_ = *(const float4*)(kgn + (long)(lkey + 32 ) * BE);
            r2_ = *(const float4*)(kgn + (long)(lkey + 64 ) * BE);
            r3_ = *(const float4*)(kgn + (long)(lkey + 96 ) * BE);
        }

        if (w < 4) {
            unsigned long long acc[4][2];
#pragma unroll
            for (int p = 0; p < 4; p++) { acc[p][0] = 0ull; acc[p][1] = 0ull; }

#pragma unroll 4
            for (int d4 = 0; d4 < 16; d4++) {
                const int c = (d4 ^ lane7) << 2;
                float4 Ka = *(const float4*)(ka_ptr + c);
                float4 Kb = *(const float4*)(kb_ptr + c);
#pragma unroll
                for (int dd = 0; dd < 4; dd++) {
                    unsigned long long kda, kdb;
                    dup2(kda, (&Ka.x)[dd]);
                    dup2(kdb, (&Kb.x)[dd]);
                    const float* qpd = qp + (((d4 * 4 + dd) * 8) + g * 4) * 2;
                    ulonglong2 q01 = *(const ulonglong2*)(qpd);
                    ulonglong2 q23 = *(const ulonglong2*)(qpd + 4);
                    fma2(acc[0][0], q01.x, kda, acc[0][0]);
                    fma2(acc[0][1], q01.x, kdb, acc[0][1]);
                    fma2(acc[1][0], q01.y, kda, acc[1][0]);
                    fma2(acc[1][1], q01.y, kdb, acc[1][1]);
                    fma2(acc[2][0], q23.x, kda, acc[2][0]);
                    fma2(acc[2][1], q23.x, kdb, acc[2][1]);
                    fma2(acc[3][0], q23.y, kda, acc[3][0]);
                    fma2(acc[3][1], q23.y, kdb, acc[3][1]);
                }
            }

            const int col = kt * KT + s * 64 + lane;
#pragma unroll
            for (int p = 0; p < 4; p++) {
                float lo, hi;
                unpack2(lo, hi, acc[p][0]);
                S[(g * 8 + 2 * p    ) * SP + col] = lo;
                S[(g * 8 + 2 * p + 1) * SP + col] = hi;
                unpack2(lo, hi, acc[p][1]);
                S[(g * 8 + 2 * p    ) * SP + col + 32] = lo;
                S[(g * 8 + 2 * p + 1) * SP + col + 32] = hi;
            }
        }
        __syncthreads();                    // readers done with ks

        if (kt < T_ / KT - 1) {
            *(float4*)&ks[(lkey      ) * 64 + lsw] = r0_;
            *(float4*)&ks[(lkey + 32 ) * 64 + ((ld4 ^ ((lkey+32) & 7)) << 2)] = r1_;
            *(float4*)&ks[(lkey + 64 ) * 64 + ((ld4 ^ ((lkey+64) & 7)) << 2)] = r2_;
            *(float4*)&ks[(lkey + 96 ) * 64 + ((ld4 ^ ((lkey+96) & 7)) << 2)] = r3_;
        }
        __syncthreads();                    // new tile visible
    }

    // ---- per-row top-16 + softmax: warp w owns row w ----
    {
        float* Sr = S + w * SP;
        const float* Sl = Sr + lane * 32;   // contiguous per-lane ownership

        float v0 = -INFINITY, v1 = -INFINITY, v2 = -INFINITY, v3 = -INFINITY;
        int   p0 = 0, p1 = 0, p2 = 0, p3 = 0;
#pragma unroll
        for (int c = 0; c < 8; c++) {
            float4 q4 = *(const float4*)(Sl + c * 4);
            const int pb = lane * 32 + c * 4;
            INS4(q4.x, pb + 0);
            INS4(q4.y, pb + 1);
            INS4(q4.z, pb + 2);
            INS4(q4.w, pb + 3);
        }
        int cnt = 4;

        unsigned kb = fmono(v0);
        unsigned mk = __reduce_max_sync(0xffffffffu, kb);
        unsigned cp = (kb == mk) ? (unsigned)p0 : 0xffffffffu;
        unsigned bp = __reduce_min_sync(0xffffffffu, cp);
        const float m = fdemono(mk);

        // softmax denominator — EXACT old pattern (bitwise identical)
        float s0 = 0.f, s1 = 0.f, s2 = 0.f, s3 = 0.f;
#pragma unroll
        for (int t = 0; t < 32; t += 4) {
            s0 += __expf(Sr[lane + 32 * (t + 0)] - m);
            s1 += __expf(Sr[lane + 32 * (t + 1)] - m);
            s2 += __expf(Sr[lane + 32 * (t + 2)] - m);
            s3 += __expf(Sr[lane + 32 * (t + 3)] - m);
        }
        float sum = (s0 + s1) + (s2 + s3);
#pragma unroll
        for (int o = 16; o; o >>= 1) sum += __shfl_xor_sync(~0u, sum, o);
        const float inv = 1.0f / sum;

        if (lane == 0) { tpi[w * TOPK] = (int)bp; tpp[w * TOPK] = inv; }
        if ((int)(bp >> 5) == lane) {
            Sr[bp] = -INFINITY;
            v0=v1;p0=p1; v1=v2;p1=p2; v2=v3;p2=p3; v3=-INFINITY;
            if (--cnt == 0) {
                v0=v1=v2=v3=-INFINITY; p0=p1=p2=p3=0;
#pragma unroll
                for (int c = 0; c < 8; c++) {
                    float4 q4 = *(const float4*)(Sl + c * 4);
                    const int pb = lane * 32 + c * 4;
                    INS4(q4.x, pb + 0);
                    INS4(q4.y, pb + 1);
                    INS4(q4.z, pb + 2);
                    INS4(q4.w, pb + 3);
                }
                cnt = 4;
            }
        }

        for (int it = 1; it < TOPK; it++) {
            kb = fmono(v0);
            mk = __reduce_max_sync(0xffffffffu, kb);
            cp = (kb == mk) ? (unsigned)p0 : 0xffffffffu;
            bp = __reduce_min_sync(0xffffffffu, cp);
            if (lane == 0) {
                tpi[w * TOPK + it] = (int)bp;
                tpp[w * TOPK + it] = __expf(fdemono(mk) - m) * inv;
            }
            if ((int)(bp >> 5) == lane) {
                Sr[bp] = -INFINITY;
                v0=v1;p0=p1; v1=v2;p1=p2; v2=v3;p2=p3; v3=-INFINITY;
                if (--cnt == 0) {
                    v0=v1=v2=v3=-INFINITY; p0=p1=p2=p3=0;
#pragma unroll
                    for (int c = 0; c < 8; c++) {
                        float4 q4 = *(const float4*)(Sl + c * 4);
                        const int pb = lane * 32 + c * 4;
                        INS4(q4.x, pb + 0);
                        INS4(q4.y, pb + 1);
                        INS4(q4.z, pb + 2);
                        INS4(q4.w, pb + 3);
                    }
                    cnt = 4;
                }
            }
        }
    }
    __syncthreads();

    // ---- sparse ctx: 16-key gather; 32 threads x float2 per row ----
    const int cr = tid >> 5;
    const int d0 = (tid & 31) * 2;
    float c0 = 0.f, c1 = 0.f;
#pragma unroll
    for (int i = 0; i < TOPK; i++) {
        const int   idx = tpi[cr * TOPK + i];
        const float p   = tpp[cr * TOPK + i];
        float2 a = *(const float2*)(vg + (long)idx * BE + base + d0);
        c0 = fmaf(p, a.x, c0); c1 = fmaf(p, a.y, c1);
    }
    *(float2*)(ctxg + (long)(qt * QT + cr) * BE + base + d0) = make_float2(c0, c1);
}

// =====================================================================
// launch
// =====================================================================
static const size_t ATTN_SMEM =
    (size_t)(QT * SP + KT * 64 + 64 * 8 * 2 + QT * TOPK + QT * TOPK) * 4;

extern "C" void kernel_launch(void* const* d_in, const int* in_sizes, int n_in,
                              void* d_out, int out_size)
{
    const float* query  = (const float*)d_in[0];
    const float* key_in = (const float*)d_in[1];
    const float* value  = (const float*)d_in[2];
    const float* Wq = (const float*)d_in[3];
    const float* bq = (const float*)d_in[4];
    const float* Wk = (const float*)d_in[5];
    const float* bk = (const float*)d_in[6];
    const float* Wv = (const float*)d_in[7];
    const float* bv = (const float*)d_in[8];
    const float* Wo = (const float*)d_in[9];
    const float* bo = (const float*)d_in[10];
    float* out = (float*)d_out;

    float *pq, *pk, *pv, *pctx;
    cudaGetSymbolAddress((void**)&pq,   g_q);
    cudaGetSymbolAddress((void**)&pk,   g_k);
    cudaGetSymbolAddress((void**)&pv,   g_v);
    cudaGetSymbolAddress((void**)&pctx, g_ctx);

    cudaFuncSetAttribute(attn_kernel,
                         cudaFuncAttributeMaxDynamicSharedMemorySize,
                         (int)ATTN_SMEM);

    dim3 gq(ROWS / 128, DIN / 128, 12);
    qkv_gemm<<<gq, 256>>>(query, key_in, value,
                          Wq, bq, Wk, bk, Wv, bv, pq, pk, pv);

    dim3 ag(T_ / QT, B_ * H_);
    attn_kernel<<<ag, NTH, ATTN_SMEM>>>(pq, pk, pv, pctx);

    dim3 go(ROWS / 128, DIN / 128, NB);
    o_gemm<<<go, 256>>>(pctx, Wo, bo, out);
}

// round 12
// speedup vs baseline: 1.3202x; 1.1462x over previous
#include <cuda_runtime.h>
#include <math.h>

#define T_   1024
#define B_   8
#define E_   1024
#define H_   16
#define HD   64
#define NB   4
#define DIN  256
#define TOPK 16
#define ROWS (T_*B_)          // 8192
#define BE   (B_*E_)          // 8192
#define SCALING 0.125f        // 64^-0.5

// ---------- scratch (device globals; no runtime allocation) ----------
__device__ float g_q[ROWS * E_];
__device__ float g_k[ROWS * E_];
__device__ float g_v[ROWS * E_];
__device__ float g_ctx[ROWS * E_];

// ---------- packed f32x2 helpers (exact lane-wise IEEE rn) ----------
__device__ __forceinline__ void dup2(unsigned long long& d, float f) {
    asm("mov.b64 %0, {%1, %1};" : "=l"(d) : "r"(__float_as_uint(f)));
}
__device__ __forceinline__ void fma2(unsigned long long& d,
                                     unsigned long long a,
                                     unsigned long long b,
                                     unsigned long long c) {
    asm("fma.rn.f32x2 %0, %1, %2, %3;" : "=l"(d) : "l"(a), "l"(b), "l"(c));
}
__device__ __forceinline__ void unpack2(float& lo, float& hi, unsigned long long p) {
    unsigned l, h;
    asm("mov.b64 {%0, %1}, %2;" : "=r"(l), "=r"(h) : "l"(p));
    lo = __uint_as_float(l); hi = __uint_as_float(h);
}

// =====================================================================
// Double-buffered block-diagonal GEMM core (BK=16, FFMA2, conflict-free
// B via paired LDS.64) — unchanged (proven 245us qkv).
// =====================================================================
__device__ __forceinline__ void gemm_core(
    const float* __restrict__ X, const float* __restrict__ W,
    const float* __restrict__ bias, float* __restrict__ Y,
    float scale, int nb)
{
    const int m0 = blockIdx.x * 128;
    const int n0 = blockIdx.y * 128;
    const float* Wn = W + nb * DIN * DIN;

    __shared__ __align__(16) float As[2][16][128];
    __shared__ __align__(16) float Bs[2][16][128];

    const int tid = threadIdx.x;
    const int ty  = tid >> 4;
    const int tx2 = (tid & 15) * 2;
    const int arow = tid >> 1;
    const int akc  = (tid & 1) * 8;
    const int bkr  = tid >> 4;
    const int bcol = (tid & 15) * 8;

    const float* Xb = X + (long)m0 * E_ + nb * DIN;
    const float* Ap = Xb + (long)arow * E_;

    {
        float4 a0 = *(const float4*)(Ap + akc);
        float4 a1 = *(const float4*)(Ap + akc + 4);
        float4 b0 = *(const float4*)(Wn + bkr * DIN + n0 + bcol);
        float4 b1 = *(const float4*)(Wn + bkr * DIN + n0 + bcol + 4);
        As[0][akc+0][arow] = a0.x; As[0][akc+1][arow] = a0.y;
        As[0][akc+2][arow] = a0.z; As[0][akc+3][arow] = a0.w;
        As[0][akc+4][arow] = a1.x; As[0][akc+5][arow] = a1.y;
        As[0][akc+6][arow] = a1.z; As[0][akc+7][arow] = a1.w;
        *(float4*)&Bs[0][bkr][bcol]     = b0;
        *(float4*)&Bs[0][bkr][bcol + 4] = b1;
    }
    __syncthreads();

    unsigned long long accp[8][4];
#pragma unroll
    for (int i = 0; i < 8; i++)
#pragma unroll
        for (int j = 0; j < 4; j++) accp[i][j] = 0ull;

    for (int k0 = 0; k0 < 16; k0++) {
        const int cur = k0 & 1;
        float4 a0, a1, b0, b1;
        if (k0 < 15) {
            const int kn = (k0 + 1) * 16;
            a0 = *(const float4*)(Ap + kn + akc);
            a1 = *(const float4*)(Ap + kn + akc + 4);
            b0 = *(const float4*)(Wn + (kn + bkr) * DIN + n0 + bcol);
            b1 = *(const float4*)(Wn + (kn + bkr) * DIN + n0 + bcol + 4);
        }
#pragma unroll
        for (int kk = 0; kk < 16; kk++) {
            float af[8];
            *(float4*)(af)     = *(const float4*)&As[cur][kk][ty * 8];
            *(float4*)(af + 4) = *(const float4*)&As[cur][kk][ty * 8 + 4];
            unsigned long long bp[4];
#pragma unroll
            for (int j = 0; j < 4; j++)
                bp[j] = *(const unsigned long long*)&Bs[cur][kk][tx2 + 32 * j];
#pragma unroll
            for (int i = 0; i < 8; i++) {
                unsigned long long aa;
                dup2(aa, af[i]);
                fma2(accp[i][0], aa, bp[0], accp[i][0]);
                fma2(accp[i][1], aa, bp[1], accp[i][1]);
                fma2(accp[i][2], aa, bp[2], accp[i][2]);
                fma2(accp[i][3], aa, bp[3], accp[i][3]);
            }
        }
        if (k0 < 15) {
            const int nxt = cur ^ 1;
            As[nxt][akc+0][arow] = a0.x; As[nxt][akc+1][arow] = a0.y;
            As[nxt][akc+2][arow] = a0.z; As[nxt][akc+3][arow] = a0.w;
            As[nxt][akc+4][arow] = a1.x; As[nxt][akc+5][arow] = a1.y;
            As[nxt][akc+6][arow] = a1.z; As[nxt][akc+7][arow] = a1.w;
            *(float4*)&Bs[nxt][bkr][bcol]     = b0;
            *(float4*)&Bs[nxt][bkr][bcol + 4] = b1;
        }
        __syncthreads();
    }

    float2 bj[4];
#pragma unroll
    for (int j = 0; j < 4; j++) {
        bj[j].x = bias[nb * DIN + n0 + tx2 + 32 * j];
        bj[j].y = bias[nb * DIN + n0 + tx2 + 32 * j + 1];
    }

#pragma unroll
    for (int i = 0; i < 8; i++) {
        const long row = m0 + ty * 8 + i;
        float* yp = Y + row * E_ + nb * DIN + n0;
#pragma unroll
        for (int j = 0; j < 4; j++) {
            float lo, hi;
            unpack2(lo, hi, accp[i][j]);
            *(float2*)(yp + tx2 + 32 * j) =
                make_float2((lo + bj[j].x) * scale, (hi + bj[j].y) * scale);
        }
    }
}

__global__ void __launch_bounds__(256) qkv_gemm(
    const float* __restrict__ Q, const float* __restrict__ Kin,
    const float* __restrict__ V,
    const float* __restrict__ Wq, const float* __restrict__ bq,
    const float* __restrict__ Wk, const float* __restrict__ bk,
    const float* __restrict__ Wv, const float* __restrict__ bv,
    float* __restrict__ Yq, float* __restrict__ Yk, float* __restrict__ Yv)
{
    const int op = blockIdx.z >> 2;
    const int nb = blockIdx.z & 3;
    if (op == 0)      gemm_core(Q,   Wq, bq, Yq, SCALING, nb);
    else if (op == 1) gemm_core(Kin, Wk, bk, Yk, 1.0f,    nb);
    else              gemm_core(V,   Wv, bv, Yv, 1.0f,    nb);
}

__global__ void __launch_bounds__(256) o_gemm(
    const float* __restrict__ X, const float* __restrict__ W,
    const float* __restrict__ bias, float* __restrict__ Y)
{
    gemm_core(X, W, bias, Y, 1.0f, blockIdx.z);
}

// =====================================================================
// Fused attention — R10 algorithm at 256 threads/block, 2 blocks/SM,
// 128 regs/thread (was 64). Score warps/roles/fma2 chains byte-identical
// to R10 -> bitwise-identical scores -> identical top-k selection.
// =====================================================================
#define QT  16
#define KT  128
#define SP  1032
#define NTH 256

__device__ __forceinline__ unsigned fmono(float f) {
    unsigned b = __float_as_uint(f);
    return (b & 0x80000000u) ? ~b : (b | 0x80000000u);
}
__device__ __forceinline__ float fdemono(unsigned m) {
    unsigned b = (m & 0x80000000u) ? (m & 0x7fffffffu) : ~m;
    return __uint_as_float(b);
}

// branchless sorted-top4 insertion; strict > keeps earliest pos on ties
#define INS4(nv, np)                                                   \
    do {                                                               \
        bool c0 = (nv) > v0, c1 = (nv) > v1,                           \
             c2 = (nv) > v2, c3 = (nv) > v3;                           \
        v3 = c3 ? (c2 ? v2 : (nv)) : v3;                               \
        p3 = c3 ? (c2 ? p2 : (np)) : p3;                               \
        v2 = c2 ? (c1 ? v1 : (nv)) : v2;                               \
        p2 = c2 ? (c1 ? p1 : (np)) : p2;                               \
        v1 = c1 ? (c0 ? v0 : (nv)) : v1;                               \
        p1 = c1 ? (c0 ? p0 : (np)) : p1;                               \
        v0 = c0 ? (nv) : v0;                                           \
        p0 = c0 ? (np) : p0;                                           \
    } while (0)

// strided conflict-free scan (positions ascend per lane -> min-pos ties)
#define SCAN_TOP4(Sr)                                                  \
    do {                                                               \
        v0 = v1 = v2 = v3 = -INFINITY;                                 \
        p0 = p1 = p2 = p3 = 0;                                         \
        _Pragma("unroll")                                              \
        for (int t = 0; t < 32; t++) {                                 \
            float nv = (Sr)[lane + 32 * t];                            \
            int   np = lane + 32 * t;                                  \
            INS4(nv, np);                                              \
        }                                                              \
    } while (0)

__global__ void __launch_bounds__(NTH, 2) attn_kernel(
    const float* __restrict__ qg, const float* __restrict__ kg,
    const float* __restrict__ vg, float* __restrict__ ctxg)
{
    extern __shared__ float sm[];
    float* S    = sm;                      // QT*SP              (66048 B)
    float* ks   = S + QT * SP;             // 128 x 64 swizzled  (32768 B)
    float* qp   = ks + KT * 64;            // [d][pair] 64 x 8 x float2 (4096 B)
    float* tpp  = qp + 64 * 8 * 2;         // QT*16
    int*   tpi  = (int*)(tpp + QT * TOPK); // QT*16

    const int tid = threadIdx.x;
    const int qt  = blockIdx.x;            // 0..63
    const int bh  = blockIdx.y;            // 0..127
    const int bb  = bh >> 4;
    const int hh  = bh & 15;
    const long base = (long)bb * E_ + hh * HD;

    const int lane = tid & 31;
    const int w    = tid >> 5;             // warp 0..7

    // ---- build q pairs: qp[(d*8+p)*2] = {q[2p][d], q[2p+1][d]} ----
#pragma unroll
    for (int e = tid; e < 512; e += NTH) {
        const int p = e >> 6;              // 0..7
        const int d = e & 63;
        const float* q0 = qg + (long)(qt * QT + 2 * p) * BE + base + d;
        *(float2*)&qp[(d * 8 + p) * 2] = make_float2(q0[0], q0[BE]);
    }

    // score warp roles (w<4): g = pair group (pairs g*4..g*4+3), s = key half
    const int g = (w >> 1) & 1;
    const int s = w & 1;
    const int lane7 = lane & 7;
    const float* ka_ptr = ks + (s * 64 + lane) * 64;
    const float* kb_ptr = ka_ptr + 32 * 64;

    for (int kt = 0; kt < T_ / KT; kt++) {
        __syncthreads();
        // loader: 8 float4 per thread per tile
#pragma unroll
        for (int f = tid; f < KT * 16; f += NTH) {
            int key = f >> 4, d4x = f & 15;
            float4 v4 = *(const float4*)(kg + (long)(kt * KT + key) * BE + base + d4x * 4);
            *(float4*)&ks[key * 64 + ((d4x ^ (key & 7)) << 2)] = v4;
        }
        __syncthreads();

        if (w < 4) {
            unsigned long long acc[4][2];
#pragma unroll
            for (int p = 0; p < 4; p++) { acc[p][0] = 0ull; acc[p][1] = 0ull; }

#pragma unroll
            for (int d4 = 0; d4 < 16; d4++) {
                const int c = (d4 ^ lane7) << 2;
                float4 Ka = *(const float4*)(ka_ptr + c);
                float4 Kb = *(const float4*)(kb_ptr + c);
#pragma unroll
                for (int dd = 0; dd < 4; dd++) {
                    unsigned long long kda, kdb;
                    dup2(kda, (&Ka.x)[dd]);
                    dup2(kdb, (&Kb.x)[dd]);
                    const float* qpd = qp + (((d4 * 4 + dd) * 8) + g * 4) * 2;
                    ulonglong2 q01 = *(const ulonglong2*)(qpd);
                    ulonglong2 q23 = *(const ulonglong2*)(qpd + 4);
                    fma2(acc[0][0], q01.x, kda, acc[0][0]);
                    fma2(acc[0][1], q01.x, kdb, acc[0][1]);
                    fma2(acc[1][0], q01.y, kda, acc[1][0]);
                    fma2(acc[1][1], q01.y, kdb, acc[1][1]);
                    fma2(acc[2][0], q23.x, kda, acc[2][0]);
                    fma2(acc[2][1], q23.x, kdb, acc[2][1]);
                    fma2(acc[3][0], q23.y, kda, acc[3][0]);
                    fma2(acc[3][1], q23.y, kdb, acc[3][1]);
                }
            }

            const int col = kt * KT + s * 64 + lane;
#pragma unroll
            for (int p = 0; p < 4; p++) {
                float lo, hi;
                unpack2(lo, hi, acc[p][0]);
                S[(g * 8 + 2 * p    ) * SP + col] = lo;
                S[(g * 8 + 2 * p + 1) * SP + col] = hi;
                unpack2(lo, hi, acc[p][1]);
                S[(g * 8 + 2 * p    ) * SP + col + 32] = lo;
                S[(g * 8 + 2 * p + 1) * SP + col + 32] = hi;
            }
        }
    }
    __syncthreads();

    // ---- per-row top-16 + softmax: warp w owns rows 2w, 2w+1 ----
    for (int r = w * 2; r < w * 2 + 2; r++) {
        float* Sr = S + r * SP;

        float v0, v1, v2, v3;
        int   p0, p1, p2, p3;
        SCAN_TOP4(Sr);
        int cnt = 4;

        unsigned kb = fmono(v0);
        unsigned mk = __reduce_max_sync(0xffffffffu, kb);
        unsigned cp = (kb == mk) ? (unsigned)p0 : 0xffffffffu;
        unsigned bp = __reduce_min_sync(0xffffffffu, cp);
        const float m = fdemono(mk);

        // softmax denominator — EXACT established pattern (bitwise identical)
        float s0 = 0.f, s1 = 0.f, s2 = 0.f, s3 = 0.f;
#pragma unroll
        for (int t = 0; t < 32; t += 4) {
            s0 += __expf(Sr[lane + 32 * (t + 0)] - m);
            s1 += __expf(Sr[lane + 32 * (t + 1)] - m);
            s2 += __expf(Sr[lane + 32 * (t + 2)] - m);
            s3 += __expf(Sr[lane + 32 * (t + 3)] - m);
        }
        float sum = (s0 + s1) + (s2 + s3);
#pragma unroll
        for (int o = 16; o; o >>= 1) sum += __shfl_xor_sync(~0u, sum, o);
        const float inv = 1.0f / sum;

        if (lane == 0) { tpi[r * TOPK] = (int)bp; tpp[r * TOPK] = inv; }
        if ((int)(bp & 31) == lane) {
            Sr[bp] = -INFINITY;
            v0=v1;p0=p1; v1=v2;p1=p2; v2=v3;p2=p3; v3=-INFINITY;
            if (--cnt == 0) { SCAN_TOP4(Sr); cnt = 4; }
        }

        for (int it = 1; it < TOPK; it++) {
            kb = fmono(v0);
            mk = __reduce_max_sync(0xffffffffu, kb);
            cp = (kb == mk) ? (unsigned)p0 : 0xffffffffu;
            bp = __reduce_min_sync(0xffffffffu, cp);
            if (lane == 0) {
                tpi[r * TOPK + it] = (int)bp;
                tpp[r * TOPK + it] = __expf(fdemono(mk) - m) * inv;
            }
            if ((int)(bp & 31) == lane) {
                Sr[bp] = -INFINITY;
                v0=v1;p0=p1; v1=v2;p1=p2; v2=v3;p2=p3; v3=-INFINITY;
                if (--cnt == 0) { SCAN_TOP4(Sr); cnt = 4; }
            }
        }
    }
    __syncthreads();

    // ---- sparse ctx: 16-key gather; 16 threads x float4 per row ----
    const int cr = tid >> 4;               // 0..15 query row
    const int d0 = (tid & 15) * 4;         // 0..60
    float c0 = 0.f, c1 = 0.f, c2 = 0.f, c3 = 0.f;
#pragma unroll
    for (int i = 0; i < TOPK; i++) {
        const int   idx = tpi[cr * TOPK + i];
        const float p   = tpp[cr * TOPK + i];
        float4 a = *(const float4*)(vg + (long)idx * BE + base + d0);
        c0 = fmaf(p, a.x, c0); c1 = fmaf(p, a.y, c1);
        c2 = fmaf(p, a.z, c2); c3 = fmaf(p, a.w, c3);
    }
    *(float4*)(ctxg + (long)(qt * QT + cr) * BE + base + d0) =
        make_float4(c0, c1, c2, c3);
}

// =====================================================================
// launch
// =====================================================================
static const size_t ATTN_SMEM =
    (size_t)(QT * SP + KT * 64 + 64 * 8 * 2 + QT * TOPK + QT * TOPK) * 4;

extern "C" void kernel_launch(void* const* d_in, const int* in_sizes, int n_in,
                              void* d_out, int out_size)
{
    const float* query  = (const float*)d_in[0];
    const float* key_in = (const float*)d_in[1];
    const float* value  = (const float*)d_in[2];
    const float* Wq = (const float*)d_in[3];
    const float* bq = (const float*)d_in[4];
    const float* Wk = (const float*)d_in[5];
    const float* bk = (const float*)d_in[6];
    const float* Wv = (const float*)d_in[7];
    const float* bv = (const float*)d_in[8];
    const float* Wo = (const float*)d_in[9];
    const float* bo = (const float*)d_in[10];
    float* out = (float*)d_out;

    float *pq, *pk, *pv, *pctx;
    cudaGetSymbolAddress((void**)&pq,   g_q);
    cudaGetSymbolAddress((void**)&pk,   g_k);
    cudaGetSymbolAddress((void**)&pv,   g_v);
    cudaGetSymbolAddress((void**)&pctx, g_ctx);

    cudaFuncSetAttribute(attn_kernel,
                         cudaFuncAttributeMaxDynamicSharedMemorySize,
                         (int)ATTN_SMEM);

    dim3 gq(ROWS / 128, DIN / 128, 12);
    qkv_gemm<<<gq, 256>>>(query, key_in, value,
                          Wq, bq, Wk, bk, Wv, bv, pq, pk, pv);

    dim3 ag(T_ / QT, B_ * H_);
    attn_kernel<<<ag, NTH, ATTN_SMEM>>>(pq, pk, pv, pctx);

    dim3 go(ROWS / 128, DIN / 128, NB);
    o_gemm<<<go, 256>>>(pctx, Wo, bo, out);
}